// round 6
// baseline (speedup 1.0000x reference)
#include <cuda_runtime.h>

// Weighted MSE over predict/target [64, 3, 17, 4096] fp32.
//   w = {1, 1, 75825} per channel (dim 1), result = sum(w*(t-p)^2) / (64*17*4096)
//
// N float4 = 3,342,336 = 256 * 13056 ; 13056 = 2^8 * 3 * 17
// Channel of float4 v = (v / 17408) % 3
//
// R6: uniform work, zero remainder. 816 blocks * 256 thr * 16 vecs covers
// NVEC exactly (816 | 13056). 816 <= 888 (6 CTAs/SM) -> still one wave.
// R5's REM path made 30% of threads do 14 pairs vs 15 -> ~7% tail; deleted.

#define NVEC        3342336
#define VEC_PER_CH  17408
#define NBLOCKS     816
#define NTHREADS    256
#define STRIDE      (NBLOCKS * NTHREADS)      // 208896
#define VPT         16                        // 16*STRIDE = 3342336 exactly
#define MAXLEN_W    75825.0f
#define INV_DENOM   (1.0f / 4456448.0f)       // 1/(64*17*4096)

__device__ float g_partials[NBLOCKS];
__device__ unsigned int g_count;              // zero-init; last block resets it

__device__ __forceinline__ float vec_term(const float4 a, const float4 b, const int v)
{
    const int ch = (v / VEC_PER_CH) % 3;
    const float w = (ch == 2) ? MAXLEN_W : 1.0f;
    const float d0 = b.x - a.x;
    const float d1 = b.y - a.y;
    const float d2 = b.z - a.z;
    const float d3 = b.w - a.w;
    return w * (d0 * d0 + d1 * d1 + d2 * d2 + d3 * d3);
}

__global__ __launch_bounds__(NTHREADS, 6) void mse_fused_kernel(
    const float4* __restrict__ predict,
    const float4* __restrict__ target,
    float* __restrict__ out)
{
    const int tid = blockIdx.x * NTHREADS + threadIdx.x;

    // Two independent accumulators: two load streams for the scheduler to
    // batch, two FMA chains.
    float s0 = 0.0f, s1 = 0.0f;
#pragma unroll
    for (int j = 0; j < VPT; j += 2) {
        const int v0 = tid + j * STRIDE;
        const int v1 = tid + (j + 1) * STRIDE;
        const float4 a0 = predict[v0];
        const float4 b0 = target[v0];
        const float4 a1 = predict[v1];
        const float4 b1 = target[v1];
        s0 += vec_term(a0, b0, v0);
        s1 += vec_term(a1, b1, v1);
    }
    float s = s0 + s1;

    // block reduce
#pragma unroll
    for (int off = 16; off > 0; off >>= 1)
        s += __shfl_down_sync(0xFFFFFFFFu, s, off);

    __shared__ float smem[NTHREADS / 32];
    const int lane = threadIdx.x & 31;
    const int wid  = threadIdx.x >> 5;
    if (lane == 0) smem[wid] = s;
    __syncthreads();

    __shared__ bool is_last;
    if (threadIdx.x == 0) {
        float bs = 0.0f;
#pragma unroll
        for (int i = 0; i < NTHREADS / 32; i++) bs += smem[i];
        g_partials[blockIdx.x] = bs;
        __threadfence();
        const unsigned int old = atomicAdd(&g_count, 1u);
        is_last = (old == NBLOCKS - 1);
    }
    __syncthreads();

    if (is_last) {
        // last arriving block: all partials are globally visible now
        float t = 0.0f;
        for (int i = threadIdx.x; i < NBLOCKS; i += NTHREADS)
            t += g_partials[i];

#pragma unroll
        for (int off = 16; off > 0; off >>= 1)
            t += __shfl_down_sync(0xFFFFFFFFu, t, off);

        if (lane == 0) smem[wid] = t;
        __syncthreads();

        if (threadIdx.x == 0) {
            float r = 0.0f;
#pragma unroll
            for (int i = 0; i < NTHREADS / 32; i++) r += smem[i];
            out[0] = r * INV_DENOM;
            g_count = 0;   // reset for next graph replay
        }
    }
}

extern "C" void kernel_launch(void* const* d_in, const int* in_sizes, int n_in,
                              void* d_out, int out_size)
{
    const float4* predict = (const float4*)d_in[0];
    const float4* target  = (const float4*)d_in[1];
    float* out = (float*)d_out;

    mse_fused_kernel<<<NBLOCKS, NTHREADS>>>(predict, target, out);
}

// round 7
// speedup vs baseline: 1.0388x; 1.0388x over previous
#include <cuda_runtime.h>

// Weighted MSE over predict/target [64, 3, 17, 4096] fp32.
//   w = {1, 1, 75825} per channel (dim 1), result = sum(w*(t-p)^2) / (64*17*4096)
//
// N float4 = 3,342,336 ; channel of float4 v = (v / 17408) % 3
//
// R7: probe warpsxMLP product between R5 (6 CTA/SM, 48 warps, 40 regs, 2 pairs)
// and R4 (4 CTA/SM, 32 warps, 64 regs, 4 pairs). 5 CTAs/SM: 740 blocks,
// 40 warps/SM, 51-reg budget -> 3 float4-pairs front-batched per thread.

#define NVEC        3342336
#define VEC_PER_CH  17408
#define NBLOCKS     740                       // 148 * 5
#define NTHREADS    256
#define STRIDE      (NBLOCKS * NTHREADS)      // 189440
#define VPT         17                        // 17*STRIDE = 3220480
#define REM         (NVEC - VPT * STRIDE)     // 121856  (< STRIDE)
#define MAXLEN_W    75825.0f
#define INV_DENOM   (1.0f / 4456448.0f)       // 1/(64*17*4096)

__device__ float g_partials[NBLOCKS];
__device__ unsigned int g_count;              // zero-init; last block resets it

__device__ __forceinline__ float vec_term(const float4 a, const float4 b, const int v)
{
    const int ch = (v / VEC_PER_CH) % 3;
    const float w = (ch == 2) ? MAXLEN_W : 1.0f;
    const float d0 = b.x - a.x;
    const float d1 = b.y - a.y;
    const float d2 = b.z - a.z;
    const float d3 = b.w - a.w;
    return w * (d0 * d0 + d1 * d1 + d2 * d2 + d3 * d3);
}

__global__ __launch_bounds__(NTHREADS, 5) void mse_fused_kernel(
    const float4* __restrict__ predict,
    const float4* __restrict__ target,
    float* __restrict__ out)
{
    const int tid = blockIdx.x * NTHREADS + threadIdx.x;

    // 3-wide explicit load batch (6 LDG.128 in flight) + rotating accumulators.
    float s0 = 0.0f, s1 = 0.0f, s2 = 0.0f;
    int j = 0;
#pragma unroll
    for (; j + 3 <= VPT; j += 3) {
        const int v0 = tid + (j + 0) * STRIDE;
        const int v1 = tid + (j + 1) * STRIDE;
        const int v2 = tid + (j + 2) * STRIDE;
        const float4 a0 = predict[v0];
        const float4 b0 = target[v0];
        const float4 a1 = predict[v1];
        const float4 b1 = target[v1];
        const float4 a2 = predict[v2];
        const float4 b2 = target[v2];
        s0 += vec_term(a0, b0, v0);
        s1 += vec_term(a1, b1, v1);
        s2 += vec_term(a2, b2, v2);
    }
#pragma unroll
    for (; j < VPT; j++) {                    // VPT%3 = 2 leftovers
        const int v = tid + j * STRIDE;
        s0 += vec_term(predict[v], target[v], v);
    }
    if (tid < REM) {
        const int v = tid + VPT * STRIDE;
        s1 += vec_term(predict[v], target[v], v);
    }
    float s = s0 + s1 + s2;

    // block reduce
#pragma unroll
    for (int off = 16; off > 0; off >>= 1)
        s += __shfl_down_sync(0xFFFFFFFFu, s, off);

    __shared__ float smem[NTHREADS / 32];
    const int lane = threadIdx.x & 31;
    const int wid  = threadIdx.x >> 5;
    if (lane == 0) smem[wid] = s;
    __syncthreads();

    __shared__ bool is_last;
    if (threadIdx.x == 0) {
        float bs = 0.0f;
#pragma unroll
        for (int i = 0; i < NTHREADS / 32; i++) bs += smem[i];
        g_partials[blockIdx.x] = bs;
        __threadfence();
        const unsigned int old = atomicAdd(&g_count, 1u);
        is_last = (old == NBLOCKS - 1);
    }
    __syncthreads();

    if (is_last) {
        // last arriving block: all partials are globally visible now
        float t = 0.0f;
        for (int i = threadIdx.x; i < NBLOCKS; i += NTHREADS)
            t += g_partials[i];

#pragma unroll
        for (int off = 16; off > 0; off >>= 1)
            t += __shfl_down_sync(0xFFFFFFFFu, t, off);

        if (lane == 0) smem[wid] = t;
        __syncthreads();

        if (threadIdx.x == 0) {
            float r = 0.0f;
#pragma unroll
            for (int i = 0; i < NTHREADS / 32; i++) r += smem[i];
            out[0] = r * INV_DENOM;
            g_count = 0;   // reset for next graph replay
        }
    }
}

extern "C" void kernel_launch(void* const* d_in, const int* in_sizes, int n_in,
                              void* d_out, int out_size)
{
    const float4* predict = (const float4*)d_in[0];
    const float4* target  = (const float4*)d_in[1];
    float* out = (float*)d_out;

    mse_fused_kernel<<<NBLOCKS, NTHREADS>>>(predict, target, out);
}